// round 15
// baseline (speedup 1.0000x reference)
#include <cuda_runtime.h>
#include <cuda_bf16.h>

// SimpleSSM closed form (A = a*I), single fused kernel:
//   z[b,d]   = (1/SEQ) * sum_s w_s x[b,s,d],  w_s = (1 - a^(SEQ-s)) / (1-a)
//   v        = (W @ C) @ B            (3 x 256, x-INDEPENDENT)
//   out[b,c] = v[c,:] . z[b,:] + bh[c]
//
// Grid 544 = 512 reduce blocks (2 seq-halves per (b,colgroup), 32 loads each,
// no atomics: disjoint half-partials) + 32 aux blocks computing v concurrently.
// launch_bounds(256,4): all 544 blocks co-resident (cap 592). The LAST block
// to arrive runs the 48-dot head, summing both half-partials of z.

#define BATCH 16
#define SEQ   4096
#define DIN   256
#define NCLS  3
#define NRED  512
#define NAUX  32
#define NBLK  (NRED + NAUX)
#define HROWS (SEQ / 2)                 // 2048 rows per half

__device__ float g_zp[2][BATCH * DIN];  // half-partials, fully rewritten
__device__ float g_t1[NCLS * DIN];      // W @ C
__device__ float g_v [NCLS * DIN];      // (W@C) @ B
__device__ unsigned g_cntA;             // aux inner barrier (monotonic)
__device__ unsigned g_cntAll;           // global arrivals   (monotonic)
__device__ unsigned g_epoch;            // bumped by head-runner at end

// ---------------------------------------------------------------------------
// Head: out[b,c] = v[c,:] . (z0[b,:]+z1[b,:]) + bh[c]   (48 dots, warp/dot)
// ---------------------------------------------------------------------------
__device__ __forceinline__ void run_head(
    const float* __restrict__ bh, float* __restrict__ out, int warp, int lane)
{
    for (int idx = warp; idx < BATCH * NCLS; idx += 8) {
        const int bb = idx / NCLS;
        const int cc = idx % NCLS;
        const float4* __restrict__ vr  = (const float4*)(g_v + (size_t)cc * DIN);
        const float4* __restrict__ z0r = (const float4*)(g_zp[0] + (size_t)bb * DIN);
        const float4* __restrict__ z1r = (const float4*)(g_zp[1] + (size_t)bb * DIN);
        float a = 0.0f;
#pragma unroll
        for (int q = 0; q < 2; q++) {
            const int li = lane + 32 * q;
            const float4 v0 = __ldcg(vr  + li);
            const float4 p0 = __ldcg(z0r + li);
            const float4 p1 = __ldcg(z1r + li);
            a += v0.x*(p0.x+p1.x) + v0.y*(p0.y+p1.y)
               + v0.z*(p0.z+p1.z) + v0.w*(p0.w+p1.w);
        }
#pragma unroll
        for (int off = 16; off > 0; off >>= 1)
            a += __shfl_down_sync(0xffffffffu, a, off);
        if (lane == 0) out[bb * NCLS + cc] = a + bh[cc];
    }
}

__global__ void __launch_bounds__(256, 4) ssm_fused_kernel(
    const float* __restrict__ x,  const float* __restrict__ A,
    const float* __restrict__ Bm, const float* __restrict__ Cm,
    const float* __restrict__ W,  const float* __restrict__ bh,
    float* __restrict__ out)
{
    const int bid  = blockIdx.x;
    const int t    = threadIdx.x;
    const int warp = t >> 5;
    const int lane = t & 31;

    // epoch read before any arrival this launch (stream/graph serialized).
    const unsigned ep     = *(volatile unsigned*)&g_epoch;
    const unsigned tgtAll = (ep + 1u) * (unsigned)NBLK;
    const unsigned tgtA   = (ep + 1u) * (unsigned)NAUX;

    // shared overlay: reduce path 12 KB / aux path 24 KB
    __shared__ __align__(16) char smraw[24 * 1024];
    __shared__ bool is_last;
    float*  wsh = (float*)smraw;                       // [HROWS]    (reduce)
    float4* red = (float4*)(smraw + HROWS * 4);        // [256]      (reduce)
    float (*ax)[24] = (float (*)[24])smraw;            // [256][24]  (aux)

    if (bid < NRED) {
        // ===================================================================
        // Reduction: half of z[b, 16 cols] per block (2048 rows, 32 loads/thr)
        // ===================================================================
        const int cg   = bid & 15;
        const int half = (bid >> 4) & 1;
        const int b    = bid >> 5;
        const int c4   = t & 3;
        const int rg   = t >> 2;            // 0..63
        const int base = half * HROWS;      // global row offset

        // ---- weights for this half: exp2 recurrence, 8 entries/thread ----
        {
            const float a = A[0];
            if (a > 0.0f && fabsf(1.0f - a) >= 1e-7f) {
                const float inv1s = (1.0f / (1.0f - a)) * (1.0f / (float)SEQ);
                const float l2a   = __log2f(a);
                // j = 7 is the largest local row -> smallest exponent k
                float e = exp2f((float)(SEQ - (base + t + 256 * 7)) * l2a);
                const float step = exp2f(256.0f * l2a);   // a^256
#pragma unroll
                for (int j = 7; j >= 0; j--) {
                    wsh[t + 256 * j] = (1.0f - e) * inv1s;
                    e *= step;                            // underflow -> inv1s
                }
            } else {
                const bool  degen = (fabsf(1.0f - a) < 1e-7f);
                const float inv1  = degen ? 0.0f : 1.0f / (1.0f - a);
#pragma unroll
                for (int j = 0; j < 8; j++) {
                    const int   rl = t + 256 * j;
                    const float k  = (float)(SEQ - (base + rl));
                    float w = degen ? k : (1.0f - powf(a, k)) * inv1;
                    wsh[rl] = w * (1.0f / (float)SEQ);
                }
            }
        }
        __syncthreads();

        const float4* __restrict__ xb =
            (const float4*)x + ((size_t)b * SEQ + base) * (DIN / 4) + cg * 4 + c4;

        float4 acc = make_float4(0.f, 0.f, 0.f, 0.f);
#pragma unroll 8
        for (int i = 0; i < HROWS / 64; i++) {
            const int   r = rg + 64 * i;              // local row in half
            const float w = wsh[r];
            const float4 v = xb[(size_t)r * (DIN / 4)];
            acc.x += w * v.x;  acc.y += w * v.y;
            acc.z += w * v.z;  acc.w += w * v.w;
        }

        red[t] = acc;
        __syncthreads();
#pragma unroll
        for (int off = 128; off >= 4; off >>= 1) {
            if (t < off) {
                float4 o4 = red[t + off];
                red[t].x += o4.x; red[t].y += o4.y;
                red[t].z += o4.z; red[t].w += o4.w;
            }
            __syncthreads();
        }
        if (t < 4) {
            ((float4*)g_zp[half])[b * (DIN / 4) + cg * 4 + t] = red[t];
        }

        // ---- arrive; last arriver runs the head ----
        __threadfence();
        __syncthreads();
        if (t == 0) {
            const unsigned old = atomicAdd(&g_cntAll, 1u);
            is_last = (old == tgtAll - 1u);
        }
        __syncthreads();
        if (is_last) {
            __threadfence();
            run_head(bh, out, warp, lane);
            __syncthreads();
            if (t == 0) atomicAdd(&g_epoch, 1u);
        }
        return;
    }

    // =======================================================================
    // Aux blocks: v = (W @ C) @ B, concurrent with the reduction.
    // =======================================================================
    const int aid = bid - NRED;             // 0..31
    const int h0  = aid * 8;                // 8 output columns per block

    // ---- stage A: t1[c, h0+j] = sum_o W[c,o] * C[o, h0+j] ----
    {
        const int o = t;
        const float w0 = W[0 * DIN + o];
        const float w1 = W[1 * DIN + o];
        const float w2 = W[2 * DIN + o];
        const float* __restrict__ Cr = Cm + (size_t)o * DIN + h0;
        float cv[8];
#pragma unroll
        for (int j = 0; j < 8; j++) cv[j] = Cr[j];
#pragma unroll
        for (int j = 0; j < 8; j++) {
            ax[t][0 * 8 + j] = w0 * cv[j];
            ax[t][1 * 8 + j] = w1 * cv[j];
            ax[t][2 * 8 + j] = w2 * cv[j];
        }
    }
    __syncthreads();
#pragma unroll
    for (int off = 128; off >= 1; off >>= 1) {
        if (t < off) {
#pragma unroll
            for (int k = 0; k < 24; k++) ax[t][k] += ax[t + off][k];
        }
        __syncthreads();
    }
    if (t < 24) {
        const int c = t >> 3, j = t & 7;
        g_t1[c * DIN + h0 + j] = ax[0][c * 8 + j];
    }

    // ---- inner barrier over the 32 aux blocks ----
    __threadfence();
    __syncthreads();
    if (t == 0) {
        atomicAdd(&g_cntA, 1u);
        volatile unsigned* c = &g_cntA;
        while (*c < tgtA) { }
    }
    __syncthreads();

    // ---- stage B: v[c, h0+j] = sum_h t1[c,h] * B[h, h0+j] ----
    {
        const int h = t;
        const float t0  = __ldcg(&g_t1[0 * DIN + h]);
        const float t1v = __ldcg(&g_t1[1 * DIN + h]);
        const float t2  = __ldcg(&g_t1[2 * DIN + h]);
        const float* __restrict__ Br = Bm + (size_t)h * DIN + h0;
        float bv[8];
#pragma unroll
        for (int j = 0; j < 8; j++) bv[j] = Br[j];
#pragma unroll
        for (int j = 0; j < 8; j++) {
            ax[t][0 * 8 + j] = t0  * bv[j];
            ax[t][1 * 8 + j] = t1v * bv[j];
            ax[t][2 * 8 + j] = t2  * bv[j];
        }
    }
    __syncthreads();
#pragma unroll
    for (int off = 128; off >= 1; off >>= 1) {
        if (t < off) {
#pragma unroll
            for (int k = 0; k < 24; k++) ax[t][k] += ax[t + off][k];
        }
        __syncthreads();
    }
    if (t < 24) {
        const int c = t >> 3, j = t & 7;
        g_v[c * DIN + h0 + j] = ax[0][c * 8 + j];
    }

    // ---- arrive; aux block could be last too ----
    __threadfence();
    __syncthreads();
    if (t == 0) {
        const unsigned old = atomicAdd(&g_cntAll, 1u);
        is_last = (old == tgtAll - 1u);
    }
    __syncthreads();
    if (is_last) {
        __threadfence();
        run_head(bh, out, warp, lane);
        __syncthreads();
        if (t == 0) atomicAdd(&g_epoch, 1u);
    }
}

// ---------------------------------------------------------------------------
extern "C" void kernel_launch(void* const* d_in, const int* in_sizes, int n_in,
                              void* d_out, int out_size) {
    const float* x  = (const float*)d_in[0];
    const float* A  = (const float*)d_in[1];
    const float* Bm = (const float*)d_in[2];
    const float* Cm = (const float*)d_in[3];
    const float* W  = (const float*)d_in[4];
    const float* bh = (const float*)d_in[5];
    float* out = (float*)d_out;

    ssm_fused_kernel<<<NBLK, 256>>>(x, A, Bm, Cm, W, bh, out);
}

// round 16
// speedup vs baseline: 1.2393x; 1.2393x over previous
#include <cuda_runtime.h>
#include <cuda_bf16.h>

// SimpleSSM closed form (A = a*I), single fused kernel:
//   z[b,d]   = (1/SEQ) * sum_s w_s x[b,s,d],  w_s = (1 - a^(SEQ-s)) / (1-a)
//   v        = (W @ C) @ B            (3 x 256, x-INDEPENDENT)
//   out[b,c] = v[c,:] . z[b,:] + bh[c]
//
// Grid 288 = 256 reduce blocks + 32 aux blocks (co-resident at 2 CTA/SM).
// Weights are a PER-THREAD register recurrence (e *= a^64 walking rows
// downward) -> no smem table, no prologue barrier, stream starts immediately.
// Aux blocks compute v concurrently; the LAST arriver runs the 48-dot head.

#define BATCH 16
#define SEQ   4096
#define DIN   256
#define NCLS  3
#define NRED  256
#define NAUX  32
#define NBLK  (NRED + NAUX)

__device__ float g_z [BATCH * DIN];   // fully rewritten every launch
__device__ float g_t1[NCLS * DIN];    // W @ C
__device__ float g_v [NCLS * DIN];    // (W@C) @ B
__device__ unsigned g_cntA;           // aux inner barrier (monotonic)
__device__ unsigned g_cntAll;         // global arrivals   (monotonic)
__device__ unsigned g_epoch;          // bumped by head-runner at end

// ---------------------------------------------------------------------------
// Head: out[b,c] = v[c,:] . z[b,:] + bh[c]  (48 dots, warp per dot)
// ---------------------------------------------------------------------------
__device__ __forceinline__ void run_head(
    const float* __restrict__ bh, float* __restrict__ out, int warp, int lane)
{
    for (int idx = warp; idx < BATCH * NCLS; idx += 8) {
        const int bb = idx / NCLS;
        const int cc = idx % NCLS;
        const float4* __restrict__ vr = (const float4*)(g_v + (size_t)cc * DIN);
        const float4* __restrict__ zr = (const float4*)(g_z + (size_t)bb * DIN);
        const float4 v0 = __ldcg(vr + lane);
        const float4 v1 = __ldcg(vr + lane + 32);
        const float4 z0 = __ldcg(zr + lane);
        const float4 z1 = __ldcg(zr + lane + 32);
        float a = v0.x*z0.x + v0.y*z0.y + v0.z*z0.z + v0.w*z0.w
                + v1.x*z1.x + v1.y*z1.y + v1.z*z1.z + v1.w*z1.w;
#pragma unroll
        for (int off = 16; off > 0; off >>= 1)
            a += __shfl_down_sync(0xffffffffu, a, off);
        if (lane == 0) out[bb * NCLS + cc] = a + bh[cc];
    }
}

__global__ void __launch_bounds__(256, 2) ssm_fused_kernel(
    const float* __restrict__ x,  const float* __restrict__ A,
    const float* __restrict__ Bm, const float* __restrict__ Cm,
    const float* __restrict__ W,  const float* __restrict__ bh,
    float* __restrict__ out)
{
    const int bid  = blockIdx.x;
    const int t    = threadIdx.x;
    const int warp = t >> 5;
    const int lane = t & 31;

    // epoch read before any arrival this launch (stream/graph serialized).
    const unsigned ep     = *(volatile unsigned*)&g_epoch;
    const unsigned tgtAll = (ep + 1u) * (unsigned)NBLK;
    const unsigned tgtA   = (ep + 1u) * (unsigned)NAUX;

    // shared overlay: reduce path uses 4 KB (red); aux path uses 24 KB (ax)
    __shared__ __align__(16) char smraw[24 * 1024];
    __shared__ bool is_last;
    float4* red = (float4*)smraw;                      // [256]      (reduce)
    float (*ax)[24] = (float (*)[24])smraw;            // [256][24]  (aux)

    if (bid < NRED) {
        // ===================================================================
        // Reduction: z[b, 16 cols] per block. Rows for this thread: rg+64*i.
        // Walk i DOWNWARD so the weight recurrence decays (e *= a^64 -> 0).
        // ===================================================================
        const int cg = bid & 15;
        const int b  = bid >> 4;
        const int c4 = t & 3;
        const int rg = t >> 2;              // 0..63

        const float4* __restrict__ xb =
            (const float4*)x + (size_t)b * SEQ * (DIN / 4) + cg * 4 + c4;

        const float a = A[0];
        float4 acc = make_float4(0.f, 0.f, 0.f, 0.f);

        if (a > 0.0f && fabsf(1.0f - a) >= 1e-7f) {
            // fast path: w_i = (1 - e_i) * inv1s, e_{i-1} = e_i * a^64
            const float inv1s = (1.0f / (1.0f - a)) * (1.0f / (float)SEQ);
            const float l2a   = __log2f(a);
            float e = exp2f((float)(64 - rg) * l2a);   // k at i=63: 64 - rg
            const float step = exp2f(64.0f * l2a);     // a^64
#pragma unroll 8
            for (int i = 63; i >= 0; i--) {
                const float w = (1.0f - e) * inv1s;
                const float4 v = xb[(size_t)(rg + 64 * i) * (DIN / 4)];
                acc.x += w * v.x;  acc.y += w * v.y;
                acc.z += w * v.z;  acc.w += w * v.w;
                e *= step;                             // underflow -> w = inv1s
            }
        } else {
            // generic path (a <= 0 or a ~= 1): per-iteration exact weights
            const bool  degen = (fabsf(1.0f - a) < 1e-7f);
            const float inv1s = degen ? 0.0f
                               : (1.0f / (1.0f - a)) * (1.0f / (float)SEQ);
            for (int i = 63; i >= 0; i--) {
                const int   r = rg + 64 * i;
                const float k = (float)(SEQ - r);
                const float w = degen ? k * (1.0f / (float)SEQ)
                                      : (1.0f - powf(a, k)) * inv1s;
                const float4 v = xb[(size_t)r * (DIN / 4)];
                acc.x += w * v.x;  acc.y += w * v.y;
                acc.z += w * v.z;  acc.w += w * v.w;
            }
        }

        red[t] = acc;
        __syncthreads();
#pragma unroll
        for (int off = 128; off >= 4; off >>= 1) {
            if (t < off) {
                float4 o4 = red[t + off];
                red[t].x += o4.x; red[t].y += o4.y;
                red[t].z += o4.z; red[t].w += o4.w;
            }
            __syncthreads();
        }
        if (t < 4) {
            ((float4*)g_z)[b * (DIN / 4) + cg * 4 + t] = red[t];
        }

        // ---- arrive; last arriver runs the head ----
        __threadfence();
        __syncthreads();
        if (t == 0) {
            const unsigned old = atomicAdd(&g_cntAll, 1u);
            is_last = (old == tgtAll - 1u);
        }
        __syncthreads();
        if (is_last) {
            __threadfence();
            run_head(bh, out, warp, lane);
            __syncthreads();
            if (t == 0) atomicAdd(&g_epoch, 1u);
        }
        return;
    }

    // =======================================================================
    // Aux blocks: v = (W @ C) @ B, concurrent with the reduction.
    // =======================================================================
    const int aid = bid - NRED;             // 0..31
    const int h0  = aid * 8;                // 8 output columns per block

    // ---- stage A: t1[c, h0+j] = sum_o W[c,o] * C[o, h0+j] ----
    {
        const int o = t;
        const float w0 = W[0 * DIN + o];
        const float w1 = W[1 * DIN + o];
        const float w2 = W[2 * DIN + o];
        const float* __restrict__ Cr = Cm + (size_t)o * DIN + h0;
        float cv[8];
#pragma unroll
        for (int j = 0; j < 8; j++) cv[j] = Cr[j];
#pragma unroll
        for (int j = 0; j < 8; j++) {
            ax[t][0 * 8 + j] = w0 * cv[j];
            ax[t][1 * 8 + j] = w1 * cv[j];
            ax[t][2 * 8 + j] = w2 * cv[j];
        }
    }
    __syncthreads();
#pragma unroll
    for (int off = 128; off >= 1; off >>= 1) {
        if (t < off) {
#pragma unroll
            for (int k = 0; k < 24; k++) ax[t][k] += ax[t + off][k];
        }
        __syncthreads();
    }
    if (t < 24) {
        const int c = t >> 3, j = t & 7;
        g_t1[c * DIN + h0 + j] = ax[0][c * 8 + j];
    }

    // ---- inner barrier over the 32 aux blocks ----
    __threadfence();
    __syncthreads();
    if (t == 0) {
        atomicAdd(&g_cntA, 1u);
        volatile unsigned* c = &g_cntA;
        while (*c < tgtA) { }
    }
    __syncthreads();

    // ---- stage B: v[c, h0+j] = sum_h t1[c,h] * B[h, h0+j] ----
    {
        const int h = t;
        const float t0  = __ldcg(&g_t1[0 * DIN + h]);
        const float t1v = __ldcg(&g_t1[1 * DIN + h]);
        const float t2  = __ldcg(&g_t1[2 * DIN + h]);
        const float* __restrict__ Br = Bm + (size_t)h * DIN + h0;
        float bv[8];
#pragma unroll
        for (int j = 0; j < 8; j++) bv[j] = Br[j];
#pragma unroll
        for (int j = 0; j < 8; j++) {
            ax[t][0 * 8 + j] = t0  * bv[j];
            ax[t][1 * 8 + j] = t1v * bv[j];
            ax[t][2 * 8 + j] = t2  * bv[j];
        }
    }
    __syncthreads();
#pragma unroll
    for (int off = 128; off >= 1; off >>= 1) {
        if (t < off) {
#pragma unroll
            for (int k = 0; k < 24; k++) ax[t][k] += ax[t + off][k];
        }
        __syncthreads();
    }
    if (t < 24) {
        const int c = t >> 3, j = t & 7;
        g_v[c * DIN + h0 + j] = ax[0][c * 8 + j];
    }

    // ---- arrive; aux block could be last too ----
    __threadfence();
    __syncthreads();
    if (t == 0) {
        const unsigned old = atomicAdd(&g_cntAll, 1u);
        is_last = (old == tgtAll - 1u);
    }
    __syncthreads();
    if (is_last) {
        __threadfence();
        run_head(bh, out, warp, lane);
        __syncthreads();
        if (t == 0) atomicAdd(&g_epoch, 1u);
    }
}

// ---------------------------------------------------------------------------
extern "C" void kernel_launch(void* const* d_in, const int* in_sizes, int n_in,
                              void* d_out, int out_size) {
    const float* x  = (const float*)d_in[0];
    const float* A  = (const float*)d_in[1];
    const float* Bm = (const float*)d_in[2];
    const float* Cm = (const float*)d_in[3];
    const float* W  = (const float*)d_in[4];
    const float* bh = (const float*)d_in[5];
    float* out = (float*)d_out;

    ssm_fused_kernel<<<NBLK, 256>>>(x, A, Bm, Cm, W, bh, out);
}